// round 8
// baseline (speedup 1.0000x reference)
#include <cuda_runtime.h>
#include <math.h>

// Problem constants
#define BB   8
#define SS   4096
#define EE   512
#define PP   64
#define LL   4
#define HH   256
#define CC   2
#define FF   2048               // 4*E
#define MROWS (BB*SS)           // 32768
#define NSPLIT 8                // S-splits for kv/z

enum { EPI_NONE = 0, EPI_PHI = 1, EPI_GELU = 2, EPI_RES = 3, EPI_DIV = 4 };

// ---------------- scratch (device globals; allocation-free) ----------------
__device__ float g_H  [(size_t)MROWS*EE];
__device__ float g_A  [(size_t)MROWS*EE];
__device__ float g_V  [(size_t)MROWS*EE];
__device__ float g_Q  [(size_t)MROWS*PP];
__device__ float g_K  [(size_t)MROWS*PP];
__device__ float g_KV [(size_t)BB*PP*EE];
__device__ float g_KVp[(size_t)NSPLIT*BB*PP*EE];
__device__ float g_Z  [(size_t)BB*PP];
__device__ float g_Zp [(size_t)NSPLIT*BB*PP];
__device__ float g_DEN[(size_t)MROWS];

// packed bf16x2 (along k): word = bf16(k even) | bf16(k odd)<<16
__device__ unsigned g_Hh [(size_t)MROWS*(EE/2)],  g_Hl [(size_t)MROWS*(EE/2)];
__device__ unsigned g_NMh[(size_t)MROWS*(EE/2)],  g_NMl[(size_t)MROWS*(EE/2)];
__device__ unsigned g_LNh[(size_t)MROWS*(EE/2)],  g_LNl[(size_t)MROWS*(EE/2)];
__device__ unsigned g_Mbh[(size_t)MROWS*(FF/2)],  g_Mbl[(size_t)MROWS*(FF/2)];
__device__ unsigned g_Qh [(size_t)MROWS*(PP/2)],  g_Ql [(size_t)MROWS*(PP/2)];
__device__ unsigned g_KVTh[(size_t)BB*EE*(PP/2)], g_KVTl[(size_t)BB*EE*(PP/2)];
// pre-split transposed weights [N][K/2]
__device__ unsigned g_Wqh[(size_t)LL*PP*(EE/2)],  g_Wql_[(size_t)LL*PP*(EE/2)];
__device__ unsigned g_Wkh[(size_t)LL*PP*(EE/2)],  g_Wkl_[(size_t)LL*PP*(EE/2)];
__device__ unsigned g_Wvh[(size_t)LL*EE*(EE/2)],  g_Wvl_[(size_t)LL*EE*(EE/2)];
__device__ unsigned g_Woh[(size_t)LL*EE*(EE/2)],  g_Wol_[(size_t)LL*EE*(EE/2)];
__device__ unsigned g_W1h[(size_t)LL*FF*(EE/2)],  g_W1l_[(size_t)LL*FF*(EE/2)];
__device__ unsigned g_W2h[(size_t)LL*EE*(FF/2)],  g_W2l_[(size_t)LL*EE*(FF/2)];

// ---------------- helpers ----------------
__device__ __forceinline__ void cp_async16(void* smem, const void* gmem) {
    unsigned sa = (unsigned)__cvta_generic_to_shared(smem);
    asm volatile("cp.async.cg.shared.global [%0], [%1], 16;" :: "r"(sa), "l"(gmem));
}
__device__ __forceinline__ void cp_commit() {
    asm volatile("cp.async.commit_group;");
}
template<int N>
__device__ __forceinline__ void cp_wait() {
    asm volatile("cp.async.wait_group %0;" :: "n"(N));
}

// Split two consecutive fp32 into packed bf16x2 hi/lo. low16 = first elem.
__device__ __forceinline__ void split2(float x, float y, unsigned& hi, unsigned& lo) {
    asm("cvt.rn.bf16x2.f32 %0, %1, %2;" : "=r"(hi) : "f"(y), "f"(x));
    float hx = __uint_as_float(hi << 16);
    float hy = __uint_as_float(hi & 0xFFFF0000u);
    float lx = x - hx;
    float ly = y - hy;
    asm("cvt.rn.bf16x2.f32 %0, %1, %2;" : "=r"(lo) : "f"(ly), "f"(lx));
}

__device__ __forceinline__ void mma_bf16(float c[4], const unsigned a[4], const unsigned b[2]) {
    asm volatile(
        "mma.sync.aligned.m16n8k16.row.col.f32.bf16.bf16.f32 "
        "{%0,%1,%2,%3}, {%4,%5,%6,%7}, {%8,%9}, {%0,%1,%2,%3};"
        : "+f"(c[0]), "+f"(c[1]), "+f"(c[2]), "+f"(c[3])
        : "r"(a[0]), "r"(a[1]), "r"(a[2]), "r"(a[3]), "r"(b[0]), "r"(b[1]));
}

// ---------------- transpose + split core ----------------
__device__ __forceinline__ void wsplit_tile(const float* Wl,
                                            unsigned* Th, unsigned* Tl,
                                            int K, int N, int k0, int n0,
                                            float (*t)[33]) {
    int tx = threadIdx.x, ty = threadIdx.y;     // 32 x 8
    #pragma unroll
    for (int i = 0; i < 4; i++)
        t[ty + i * 8][tx] = Wl[(size_t)(k0 + ty + i * 8) * N + n0 + tx];
    __syncthreads();
    int tid = ty * 32 + tx;
    #pragma unroll
    for (int i = 0; i < 2; i++) {
        int w = tid + i * 256;
        int n = w >> 4, kp = w & 15;
        unsigned h, l;
        split2(t[2 * kp][n], t[2 * kp + 1][n], h, l);
        size_t o = (size_t)(n0 + n) * (K >> 1) + (k0 >> 1) + kp;
        Th[o] = h;
        Tl[o] = l;
    }
}

// generic single-matrix version (batched over blockIdx.z) — used for KV transpose
__global__ void wsplit_kernel(const float* __restrict__ W,
                              unsigned* __restrict__ Th, unsigned* __restrict__ Tl,
                              int K, int N) {
    __shared__ float t[32][33];
    wsplit_tile(W + (size_t)blockIdx.z * K * N,
                Th + (size_t)blockIdx.z * N * (K >> 1),
                Tl + (size_t)blockIdx.z * N * (K >> 1),
                K, N, blockIdx.y * 32, blockIdx.x * 32, t);
}

// multi-matrix version: up to 4 weight tensors (each with LL layers) in one launch
struct WSEntry { const float* W; unsigned* Th; unsigned* Tl; int K; int N; int nblk; };
struct WSPack  { WSEntry e[4]; int cnt; };

__global__ void wsplit_multi(WSPack p) {
    __shared__ float t[32][33];
    int bid = blockIdx.x;
    int i = 0;
    while (i + 1 < p.cnt && bid >= p.e[i].nblk) { bid -= p.e[i].nblk; i++; }
    WSEntry E = p.e[i];
    int tiles_n = E.N / 32;
    int tpl = tiles_n * (E.K / 32);
    int layer = bid / tpl, rem = bid % tpl;
    int k0 = (rem / tiles_n) * 32, n0 = (rem % tiles_n) * 32;
    wsplit_tile(E.W + (size_t)layer * E.K * E.N,
                E.Th + (size_t)layer * E.N * (E.K >> 1),
                E.Tl + (size_t)layer * E.N * (E.K >> 1),
                E.K, E.N, k0, n0, t);
}

// ---------------- embedding + positional (fp32 + packed) ----------------
__global__ void embed_kernel(const int* __restrict__ x,
                             const float* __restrict__ emb,
                             const float* __restrict__ pos,
                             float* __restrict__ H,
                             unsigned* __restrict__ Hh, unsigned* __restrict__ Hl) {
    int row = blockIdx.x;
    int s   = row & (SS - 1);
    int tok = x[row];
    const float4* e4 = (const float4*)(emb + (size_t)tok * EE);
    const float4* p4 = (const float4*)(pos + (size_t)s * EE);
    int t = threadIdx.x;                    // 128, 4 elems each
    float4 a = e4[t], b = p4[t];
    float4 o = make_float4(a.x + b.x, a.y + b.y, a.z + b.z, a.w + b.w);
    ((float4*)(H + (size_t)row * EE))[t] = o;
    unsigned h0, l0, h1, l1;
    split2(o.x, o.y, h0, l0);
    split2(o.z, o.w, h1, l1);
    size_t wo = (size_t)row * (EE / 2) + 2 * t;
    Hh[wo] = h0; Hh[wo + 1] = h1;
    Hl[wo] = l0; Hl[wo + 1] = l1;
}

// ---------------- packed-operand bf16x2 tensor-core GEMM ----------------
// C[M,N] = A[M,K] @ B[K,N]. A packed hi/lo [M][K/2] words;
// B packed transposed hi/lo [N][K/2] words. BK=32, 3-stage cp.async.
// Split MMAs are term-grouped (all hh, then hl, then lh) so consecutive
// instructions never share an accumulator (RAW-chain distance = MT*NT).
template<int BM, int BN, int WM, int WN, int EPI, bool WF32, bool WPACK, bool BATCHB>
__global__ void __launch_bounds__((BM/WM)*(BN/WN)*32)
gemm_pk(int M, int N, int K,
        const unsigned* __restrict__ Ah, const unsigned* __restrict__ Al,
        const unsigned* __restrict__ Bh, const unsigned* __restrict__ Bl,
        const float* __restrict__ bias,        // bias[N], or inv[M] for EPI_DIV
        const float* __restrict__ res,
        float* __restrict__ C,
        unsigned* __restrict__ Ch, unsigned* __restrict__ Cl)
{
    constexpr int WARPS_M = BM / WM;
    constexpr int WARPS_N = BN / WN;
    constexpr int NTH = WARPS_M * WARPS_N * 32;
    constexpr int LDW = 20;            // 16 words + 4 pad per row
    constexpr int ASZ = BM * LDW;
    constexpr int BSZ = BN * LDW;
    constexpr int MT = WM / 16;
    constexpr int NT = WN / 8;
    constexpr int A_CNT = BM * 4 / NTH;   // 16B chunks per stage per array
    constexpr int B_CNT = BN * 4 / NTH;

    extern __shared__ unsigned smw[];
    unsigned* Ash = smw;
    unsigned* Asl = smw + 3 * ASZ;
    unsigned* Bsh = smw + 6 * ASZ;
    unsigned* Bsl = smw + 6 * ASZ + 3 * BSZ;

    const int tid  = threadIdx.x;
    const int lane = tid & 31;
    const int warp = tid >> 5;
    const int wm   = warp / WARPS_N;
    const int wn   = warp % WARPS_N;
    const int lr   = lane >> 2;
    const int lc   = lane & 3;
    const int row0 = blockIdx.y * BM;
    const int col0 = blockIdx.x * BN;
    const int KW   = K >> 1;
    const int KT   = K / 32;

    const unsigned* Bhp = Bh;
    const unsigned* Blp = Bl;
    if (BATCHB) {
        size_t boff = (size_t)(blockIdx.y / (SS / BM)) * N * KW;
        Bhp += boff;
        Blp += boff;
    }

    float acc[MT][NT][4];
    #pragma unroll
    for (int i = 0; i < MT; i++)
        #pragma unroll
        for (int j = 0; j < NT; j++)
            #pragma unroll
            for (int q = 0; q < 4; q++) acc[i][j][q] = 0.f;

    auto issue = [&](int kt, int st) {
        int goff = kt * 16;
        #pragma unroll
        for (int i = 0; i < A_CNT; i++) {
            int idx = tid + i * NTH;
            int r = idx >> 2, c = (idx & 3) * 4;
            size_t g = (size_t)(row0 + r) * KW + goff + c;
            cp_async16(Ash + st * ASZ + r * LDW + c, Ah + g);
            cp_async16(Asl + st * ASZ + r * LDW + c, Al + g);
        }
        #pragma unroll
        for (int i = 0; i < B_CNT; i++) {
            int idx = tid + i * NTH;
            int r = idx >> 2, c = (idx & 3) * 4;
            size_t g = (size_t)(col0 + r) * KW + goff + c;
            cp_async16(Bsh + st * BSZ + r * LDW + c, Bhp + g);
            cp_async16(Bsl + st * BSZ + r * LDW + c, Blp + g);
        }
    };

    auto compute = [&](int st) {
        const unsigned* Ah_ = Ash + st * ASZ;
        const unsigned* Al_ = Asl + st * ASZ;
        const unsigned* Bh_ = Bsh + st * BSZ;
        const unsigned* Bl_ = Bsl + st * BSZ;
        #pragma unroll
        for (int kk = 0; kk < 2; kk++) {
            unsigned ah[MT][4], al[MT][4], bh[NT][2], bl[NT][2];
            #pragma unroll
            for (int i = 0; i < MT; i++) {
                int base = (wm * WM + i * 16 + lr) * LDW + kk * 8 + lc;
                ah[i][0] = Ah_[base];               al[i][0] = Al_[base];
                ah[i][1] = Ah_[base + 8 * LDW];     al[i][1] = Al_[base + 8 * LDW];
                ah[i][2] = Ah_[base + 4];           al[i][2] = Al_[base + 4];
                ah[i][3] = Ah_[base + 8 * LDW + 4]; al[i][3] = Al_[base + 8 * LDW + 4];
            }
            #pragma unroll
            for (int j = 0; j < NT; j++) {
                int bbase = (wn * WN + j * 8 + lr) * LDW + kk * 8 + lc;
                bh[j][0] = Bh_[bbase];     bl[j][0] = Bl_[bbase];
                bh[j][1] = Bh_[bbase + 4]; bl[j][1] = Bl_[bbase + 4];
            }
            // term-grouped: consecutive MMAs never share an accumulator
            #pragma unroll
            for (int i = 0; i < MT; i++)
                #pragma unroll
                for (int j = 0; j < NT; j++)
                    mma_bf16(acc[i][j], ah[i], bh[j]);
            #pragma unroll
            for (int i = 0; i < MT; i++)
                #pragma unroll
                for (int j = 0; j < NT; j++)
                    mma_bf16(acc[i][j], ah[i], bl[j]);
            #pragma unroll
            for (int i = 0; i < MT; i++)
                #pragma unroll
                for (int j = 0; j < NT; j++)
                    mma_bf16(acc[i][j], al[i], bh[j]);
        }
    };

    issue(0, 0); cp_commit();
    issue(1, 1); cp_commit();
    cp_wait<1>();
    __syncthreads();

    for (int kt = 0; kt < KT; kt++) {
        if (kt + 2 < KT) issue(kt + 2, (kt + 2) % 3);
        cp_commit();
        compute(kt % 3);
        cp_wait<1>();
        __syncthreads();
    }

    auto epi = [&](float v, int rr, int cc) -> float {
        if (EPI == EPI_PHI) {
            return v > 0.f ? v + 1.f : expf(v);
        } else if (EPI == EPI_GELU) {
            v += bias[cc];
            float u = 0.7978845608028654f * (v + 0.044715f * v * v * v);
            return 0.5f * v * (1.f + tanhf(u));
        } else if (EPI == EPI_RES) {
            return v + bias[cc] + res[(size_t)rr * N + cc];
        } else if (EPI == EPI_DIV) {
            return v * bias[rr];
        }
        return v;
    };

    #pragma unroll
    for (int i = 0; i < MT; i++) {
        #pragma unroll
        for (int j = 0; j < NT; j++) {
            int rr = row0 + wm * WM + i * 16 + lr;
            int cc = col0 + wn * WN + j * 8 + 2 * lc;
            float e00 = epi(acc[i][j][0], rr, cc);
            float e01 = epi(acc[i][j][1], rr, cc + 1);
            float e10 = epi(acc[i][j][2], rr + 8, cc);
            float e11 = epi(acc[i][j][3], rr + 8, cc + 1);
            if (WF32) {
                *(float2*)(C + (size_t)rr * N + cc)       = make_float2(e00, e01);
                *(float2*)(C + (size_t)(rr + 8) * N + cc) = make_float2(e10, e11);
            }
            if (WPACK) {
                unsigned h, l;
                split2(e00, e01, h, l);
                size_t w0 = (size_t)rr * (N >> 1) + (cc >> 1);
                Ch[w0] = h; Cl[w0] = l;
                split2(e10, e11, h, l);
                size_t w1 = (size_t)(rr + 8) * (N >> 1) + (cc >> 1);
                Ch[w1] = h; Cl[w1] = l;
            }
        }
    }
}

// ---------------- kv partials: split over S ----------------
__global__ void __launch_bounds__(256)
kv_kernel(const float* __restrict__ Kp, const float* __restrict__ V,
          float* __restrict__ KVp)
{
    int b  = blockIdx.y;
    int f0 = blockIdx.x * 64;
    int sp = blockIdx.z;
    const float* Kb = Kp + (size_t)b * SS * PP;
    const float* Vb = V  + (size_t)b * SS * EE;

    __shared__ float Ks[32 * 64];
    __shared__ float Vs[32 * 64];
    int tid = threadIdx.x;
    int tx = tid % 16, ty = tid / 16;

    float acc[4][4];
    #pragma unroll
    for (int i = 0; i < 4; i++)
        #pragma unroll
        for (int j = 0; j < 4; j++) acc[i][j] = 0.f;

    int sbeg = sp * (SS / NSPLIT), send = sbeg + (SS / NSPLIT);
    for (int s0 = sbeg; s0 < send; s0 += 32) {
        #pragma unroll
        for (int i = 0; i < 2; i++) {
            int idx = tid + i * 256;
            int r = idx / 16, c4 = idx % 16;
            *(float4*)(Ks + r * 64 + c4 * 4) =
                *(const float4*)(Kb + (size_t)(s0 + r) * PP + c4 * 4);
            *(float4*)(Vs + r * 64 + c4 * 4) =
                *(const float4*)(Vb + (size_t)(s0 + r) * EE + f0 + c4 * 4);
        }
        __syncthreads();
        #pragma unroll
        for (int k = 0; k < 32; k++) {
            float rp[4], rv[4];
            #pragma unroll
            for (int i = 0; i < 4; i++) rp[i] = Ks[k * 64 + ty * 4 + i];
            #pragma unroll
            for (int j = 0; j < 4; j++) rv[j] = Vs[k * 64 + tx * 4 + j];
            #pragma unroll
            for (int i = 0; i < 4; i++)
                #pragma unroll
                for (int j = 0; j < 4; j++)
                    acc[i][j] = fmaf(rp[i], rv[j], acc[i][j]);
        }
        __syncthreads();
    }
    float* out = KVp + (size_t)sp * BB * PP * EE;
    #pragma unroll
    for (int i = 0; i < 4; i++)
        #pragma unroll
        for (int j = 0; j < 4; j++)
            out[((size_t)b * PP + ty * 4 + i) * EE + f0 + tx * 4 + j] = acc[i][j];
}

__global__ void reduce_kv(const float* __restrict__ KVp, float* __restrict__ KV) {
    size_t idx = (size_t)blockIdx.x * 256 + threadIdx.x;
    float s = 0.f;
    #pragma unroll
    for (int sp = 0; sp < NSPLIT; sp++)
        s += KVp[(size_t)sp * BB * PP * EE + idx];
    KV[idx] = s;
}

// ---------------- z partials ----------------
__global__ void z_kernel(const float* __restrict__ Kp, float* __restrict__ Zp) {
    int b = blockIdx.x, sp = blockIdx.y;
    int tid = threadIdx.x;
    int p = tid & 63, g = tid >> 6;
    const float* Kb = Kp + (size_t)b * SS * PP;
    float acc = 0.f;
    int sbeg = sp * (SS / NSPLIT), send = sbeg + (SS / NSPLIT);
    for (int s = sbeg + g; s < send; s += 4) acc += Kb[(size_t)s * PP + p];
    __shared__ float smem[256];
    smem[tid] = acc;
    __syncthreads();
    if (g == 0)
        Zp[(size_t)sp * BB * PP + b * PP + p] =
            smem[p] + smem[64 + p] + smem[128 + p] + smem[192 + p];
}

__global__ void reduce_z(const float* __restrict__ Zp, float* __restrict__ Z) {
    int idx = blockIdx.x * 256 + threadIdx.x;
    if (idx < BB * PP) {
        float s = 0.f;
        #pragma unroll
        for (int sp = 0; sp < NSPLIT; sp++) s += Zp[sp * BB * PP + idx];
        Z[idx] = s;
    }
}

// ---------------- den: inv[row] = 1/(phi_q[row] . z[b] + eps) ----------------
__global__ void den_kernel(const float* __restrict__ Q,
                           const float* __restrict__ Z,
                           float* __restrict__ inv) {
    int row  = blockIdx.x * 8 + (threadIdx.x >> 5);
    int lane = threadIdx.x & 31;
    int b    = row >> 12;                  // / SS
    const float* q = Q + (size_t)row * PP;
    const float* z = Z + b * PP;
    float s = q[lane] * z[lane] + q[lane + 32] * z[lane + 32];
    #pragma unroll
    for (int o = 16; o; o >>= 1) s += __shfl_xor_sync(0xffffffffu, s, o);
    if (lane == 0) inv[row] = 1.f / (s + 1e-6f);
}

// ---------------- layernorm: read fp32, write packed ----------------
__global__ void ln_kernel(const float* __restrict__ X,
                          const float* __restrict__ gam,
                          const float* __restrict__ bet,
                          unsigned* __restrict__ Oh, unsigned* __restrict__ Ol) {
    int row = blockIdx.x;
    const float* xr = X + (size_t)row * EE;
    int tid = threadIdx.x;                 // 128
    float4 v = ((const float4*)xr)[tid];
    float s = v.x + v.y + v.z + v.w;
    float q = v.x * v.x + v.y * v.y + v.z * v.z + v.w * v.w;
    #pragma unroll
    for (int o = 16; o; o >>= 1) {
        s += __shfl_xor_sync(0xffffffffu, s, o);
        q += __shfl_xor_sync(0xffffffffu, q, o);
    }
    __shared__ float ss[4], qq[4];
    int w = tid >> 5;
    if ((tid & 31) == 0) { ss[w] = s; qq[w] = q; }
    __syncthreads();
    s = ss[0] + ss[1] + ss[2] + ss[3];
    q = qq[0] + qq[1] + qq[2] + qq[3];
    float mu  = s * (1.f / EE);
    float var = q * (1.f / EE) - mu * mu;
    float inv = rsqrtf(var + 1e-5f);
    float4 g4 = ((const float4*)gam)[tid];
    float4 b4 = ((const float4*)bet)[tid];
    float o0 = (v.x - mu) * inv * g4.x + b4.x;
    float o1 = (v.y - mu) * inv * g4.y + b4.y;
    float o2 = (v.z - mu) * inv * g4.z + b4.z;
    float o3 = (v.w - mu) * inv * g4.w + b4.w;
    unsigned h0, l0, h1, l1;
    split2(o0, o1, h0, l0);
    split2(o2, o3, h1, l1);
    size_t wo = (size_t)row * (EE / 2) + 2 * tid;
    Oh[wo] = h0; Oh[wo + 1] = h1;
    Ol[wo] = l0; Ol[wo + 1] = l1;
}

// ---------------- head ----------------
__global__ void head_kernel(const float* __restrict__ Hm,
                            const float* __restrict__ Wh1,
                            const float* __restrict__ bh1,
                            const float* __restrict__ Wh2,
                            const float* __restrict__ bh2,
                            float* __restrict__ out) {
    int b = blockIdx.x;
    int tid = threadIdx.x;
    const float* hr = Hm + (size_t)b * SS * EE;
    float acc = bh1[tid];
    for (int e = 0; e < EE; e++) acc = fmaf(hr[e], Wh1[e * HH + tid], acc);
    acc = fmaxf(acc, 0.f);
    __shared__ float hid[HH];
    hid[tid] = acc;
    __syncthreads();
    if (tid < CC) {
        float a = bh2[tid];
        for (int h = 0; h < HH; h++) a = fmaf(hid[h], Wh2[h * CC + tid], a);
        out[b * CC + tid] = a;
    }
}

// ---------------- launch ----------------
static size_t gemm_smem(int BM, int BN) {
    return (size_t)(3 * (BM * 20 * 2 + BN * 20 * 2)) * 4;
}

extern "C" void kernel_launch(void* const* d_in, const int* in_sizes, int n_in,
                              void* d_out, int out_size) {
    const int*   x    = (const int*)  d_in[0];
    const float* emb  = (const float*)d_in[1];
    const float* pos  = (const float*)d_in[2];
    const float* Wq   = (const float*)d_in[3];
    const float* Wk   = (const float*)d_in[4];
    const float* Wv   = (const float*)d_in[5];
    const float* Wo   = (const float*)d_in[6];
    const float* ln_g = (const float*)d_in[7];
    const float* ln_b = (const float*)d_in[8];
    const float* W1   = (const float*)d_in[9];
    const float* b1   = (const float*)d_in[10];
    const float* W2   = (const float*)d_in[11];
    const float* b2   = (const float*)d_in[12];
    const float* Wh1  = (const float*)d_in[13];
    const float* bh1  = (const float*)d_in[14];
    const float* Wh2  = (const float*)d_in[15];
    const float* bh2  = (const float*)d_in[16];
    float* out = (float*)d_out;

    float *H, *A, *V, *Q, *Kq, *KV, *KVp, *Z, *Zp, *DEN;
    cudaGetSymbolAddress((void**)&H,   g_H);
    cudaGetSymbolAddress((void**)&A,   g_A);
    cudaGetSymbolAddress((void**)&V,   g_V);
    cudaGetSymbolAddress((void**)&Q,   g_Q);
    cudaGetSymbolAddress((void**)&Kq,  g_K);
    cudaGetSymbolAddress((void**)&KV,  g_KV);
    cudaGetSymbolAddress((void**)&KVp, g_KVp);
    cudaGetSymbolAddress((void**)&Z,   g_Z);
    cudaGetSymbolAddress((void**)&Zp,  g_Zp);
    cudaGetSymbolAddress((void**)&DEN, g_DEN);

    unsigned *Hh, *Hl, *NMh, *NMl, *LNh, *LNl, *Mbh, *Mbl, *Qh, *Ql, *KVTh, *KVTl;
    cudaGetSymbolAddress((void**)&Hh,  g_Hh);  cudaGetSymbolAddress((void**)&Hl,  g_Hl);
    cudaGetSymbolAddress((void**)&NMh, g_NMh); cudaGetSymbolAddress((void**)&NMl, g_NMl);
    cudaGetSymbolAddress((void**)&LNh, g_LNh); cudaGetSymbolAddress((void**)&LNl, g_LNl);
    cudaGetSymbolAddress((void**)&Mbh, g_Mbh); cudaGetSymbolAddress((void**)&Mbl, g_Mbl);
    cudaGetSymbolAddress((void**)&Qh,  g_Qh);  cudaGetSymbolAddress((void**)&Ql,  g_Ql);
    cudaGetSymbolAddress((void**)&KVTh, g_KVTh); cudaGetSymbolAddress((void**)&KVTl, g_KVTl);

    unsigned *Wqh, *Wql, *Wkh, *Wkl, *Wvh, *Wvl, *Woh, *Wol, *W1h, *W1l, *W2h, *W2l;
    cudaGetSymbolAddress((void**)&Wqh, g_Wqh); cudaGetSymbolAddress((void**)&Wql, g_Wql_);
    cudaGetSymbolAddress((void**)&Wkh, g_Wkh); cudaGetSymbolAddress((void**)&Wkl, g_Wkl_);
    cudaGetSymbolAddress((void**)&Wvh, g_Wvh); cudaGetSymbolAddress((void**)&Wvl, g_Wvl_);
    cudaGetSymbolAddress((void**)&Woh, g_Woh); cudaGetSymbolAddress((void**)&Wol, g_Wol_);
    cudaGetSymbolAddress((void**)&W1h, g_W1h); cudaGetSymbolAddress((void**)&W1l, g_W1l_);
    cudaGetSymbolAddress((void**)&W2h, g_W2h); cudaGetSymbolAddress((void**)&W2l, g_W2l_);

    const size_t smQK  = gemm_smem(128, 64);    //  92,160 B
    const size_t smBIG = gemm_smem(128, 256);   // 184,320 B
    cudaFuncSetAttribute(gemm_pk<128, 64, 32, 32, EPI_PHI, true, true, false>,
                         cudaFuncAttributeMaxDynamicSharedMemorySize, (int)smQK);
    cudaFuncSetAttribute(gemm_pk<128, 64, 32, 32, EPI_PHI, true, false, false>,
                         cudaFuncAttributeMaxDynamicSharedMemorySize, (int)smQK);
    cudaFuncSetAttribute(gemm_pk<128, 256, 64, 32, EPI_NONE, true, false, false>,
                         cudaFuncAttributeMaxDynamicSharedMemorySize, (int)smBIG);
    cudaFuncSetAttribute(gemm_pk<128, 256, 64, 32, EPI_DIV, false, true, true>,
                         cudaFuncAttributeMaxDynamicSharedMemorySize, (int)smBIG);
    cudaFuncSetAttribute(gemm_pk<128, 256, 64, 32, EPI_GELU, false, true, false>,
                         cudaFuncAttributeMaxDynamicSharedMemorySize, (int)smBIG);
    cudaFuncSetAttribute(gemm_pk<128, 256, 64, 32, EPI_RES, true, true, false>,
                         cudaFuncAttributeMaxDynamicSharedMemorySize, (int)smBIG);

    // one-time weight transpose+split: 2 combined launches (keeps launch #5 = V GEMM)
    dim3 wt(32, 8);
    {
        WSPack pA;
        pA.e[0] = { Wq, Wqh, Wql, EE, PP, LL * (EE / 32) * (PP / 32) };
        pA.e[1] = { Wk, Wkh, Wkl, EE, PP, LL * (EE / 32) * (PP / 32) };
        pA.e[2] = { Wv, Wvh, Wvl, EE, EE, LL * (EE / 32) * (EE / 32) };
        pA.e[3] = { Wo, Woh, Wol, EE, EE, LL * (EE / 32) * (EE / 32) };
        pA.cnt = 4;
        int nA = pA.e[0].nblk + pA.e[1].nblk + pA.e[2].nblk + pA.e[3].nblk;
        wsplit_multi<<<nA, wt>>>(pA);

        WSPack pB;
        pB.e[0] = { W1, W1h, W1l, EE, FF, LL * (EE / 32) * (FF / 32) };
        pB.e[1] = { W2, W2h, W2l, FF, EE, LL * (FF / 32) * (EE / 32) };
        pB.e[2] = pB.e[0]; pB.e[3] = pB.e[0];
        pB.cnt = 2;
        int nB = pB.e[0].nblk + pB.e[1].nblk;
        wsplit_multi<<<nB, wt>>>(pB);
    }

    embed_kernel<<<MROWS, 128>>>(x, emb, pos, H, Hh, Hl);

    for (int l = 0; l < LL; l++) {
        size_t oQK = (size_t)l * PP * (EE / 2);
        size_t oV  = (size_t)l * EE * (EE / 2);
        size_t oW1 = (size_t)l * FF * (EE / 2);
        size_t oW2 = (size_t)l * EE * (FF / 2);

        // phi_q: fp32 (for den) + packed (for num GEMM)
        gemm_pk<128, 64, 32, 32, EPI_PHI, true, true, false>
            <<<dim3(PP / 64, MROWS / 128), 256, smQK>>>(
                MROWS, PP, EE, Hh, Hl, Wqh + oQK, Wql + oQK,
                nullptr, nullptr, Q, Qh, Ql);
        gemm_pk<128, 64, 32, 32, EPI_PHI, true, false, false>
            <<<dim3(PP / 64, MROWS / 128), 256, smQK>>>(
                MROWS, PP, EE, Hh, Hl, Wkh + oQK, Wkl + oQK,
                nullptr, nullptr, Kq, nullptr, nullptr);
        gemm_pk<128, 256, 64, 32, EPI_NONE, true, false, false>
            <<<dim3(EE / 256, MROWS / 128), 512, smBIG>>>(
                MROWS, EE, EE, Hh, Hl, Wvh + oV, Wvl + oV,
                nullptr, nullptr, V, nullptr, nullptr);

        kv_kernel<<<dim3(EE / 64, BB, NSPLIT), 256>>>(Kq, V, KVp);
        z_kernel<<<dim3(BB, NSPLIT), 256>>>(Kq, Zp);
        reduce_kv<<<(BB * PP * EE) / 256, 256>>>(KVp, KV);
        reduce_z<<<2, 256>>>(Zp, Z);
        // KV [b][P][E] -> packed transposed [b][E][P/2]
        wsplit_kernel<<<dim3(EE / 32, PP / 32, BB), wt>>>(KV, KVTh, KVTl, PP, EE);
        den_kernel<<<MROWS / 8, 256>>>(Q, Z, DEN);

        // num/den via tensor GEMM: attn = (phi_q @ KV) * inv[row], packed out
        gemm_pk<128, 256, 64, 32, EPI_DIV, false, true, true>
            <<<dim3(EE / 256, MROWS / 128), 512, smBIG>>>(
                MROWS, EE, PP, Qh, Ql, KVTh, KVTl,
                DEN, nullptr, nullptr, NMh, NMl);

        gemm_pk<128, 256, 64, 32, EPI_NONE, true, false, false>
            <<<dim3(EE / 256, MROWS / 128), 512, smBIG>>>(
                MROWS, EE, EE, NMh, NMl, Woh + oV, Wol + oV,
                nullptr, nullptr, A, nullptr, nullptr);

        ln_kernel<<<MROWS, 128>>>(A, ln_g + (size_t)l * EE, ln_b + (size_t)l * EE,
                                  LNh, LNl);

        gemm_pk<128, 256, 64, 32, EPI_GELU, false, true, false>
            <<<dim3(FF / 256, MROWS / 128), 512, smBIG>>>(
                MROWS, FF, EE, LNh, LNl, W1h + oW1, W1l + oW1,
                b1 + (size_t)l * FF, nullptr, nullptr, Mbh, Mbl);
        gemm_pk<128, 256, 64, 32, EPI_RES, true, true, false>
            <<<dim3(EE / 256, MROWS / 128), 512, smBIG>>>(
                MROWS, EE, FF, Mbh, Mbl, W2h + oW2, W2l + oW2,
                b2 + (size_t)l * EE, H, H, Hh, Hl);
    }

    head_kernel<<<BB, HH>>>(H, Wh1, bh1, Wh2, bh2, out);
}